// round 12
// baseline (speedup 1.0000x reference)
#include <cuda_runtime.h>

#define F_NUM 20000
#define H_NUM 40000
#define NALL  60000
#define E_NUM 640000
#define D_DIM 128
#define A_DIM 64
#define B_NUM 256
#define KSPLIT 50
#define KCH (F_NUM / KSPLIT)   // 400

// pmma tiling: 64 rows per block (A tile staged in smem), 8 warps:
// 4 M-groups (16 rows) x 2 N-halves (32 cols).
#define PM_ROWS 64
#define PB1M ((F_NUM + PM_ROWS - 1) / PM_ROWS)   // 313
#define PB2M ((NALL + PM_ROWS - 1) / PM_ROWS)    // 938
#define SA_STRIDE 132   // 128 + 4 pad -> conflict-free fragment LDS

static_assert(KSPLIT * KCH == F_NUM, "split-K must tile F exactly");
static_assert(KCH % 8 == 0, "mma k-chunk must be a multiple of 8");

// ---- scratch (static device globals; no allocation) ----
__device__ float    g_P1[F_NUM * A_DIM];
__device__ float    g_P2[NALL * A_DIM];
__device__ float    g_context[F_NUM * D_DIM];
__device__ int      g_cp[E_NUM];
__device__ int      g_fci[E_NUM];
__device__ int      g_is32[2];
__device__ int      g_segstart[F_NUM + 1];
__device__ float    g_partial[KSPLIT * B_NUM * D_DIM];
__device__ unsigned g_Whi[2 * D_DIM * A_DIM];
__device__ unsigned g_Wlo[2 * D_DIM * A_DIM];

__device__ __forceinline__ float tanh_hw(float x) {
    float y;
    asm("tanh.approx.f32 %0, %1;" : "=f"(y) : "f"(x));
    return y;
}

// tf32 helpers for 3xTF32 GEMM
__device__ __forceinline__ unsigned tf32_of(float x) {
    unsigned r;
    asm("cvt.rna.tf32.f32 %0, %1;" : "=r"(r) : "f"(x));
    return r;
}
__device__ __forceinline__ void tf32_split(float x, unsigned& hi, unsigned& lo) {
    hi = tf32_of(x);
    lo = tf32_of(x - __uint_as_float(hi));
}
__device__ __forceinline__ void mma_tf32(float* d, const unsigned* a, const unsigned* b) {
    asm volatile(
        "mma.sync.aligned.m16n8k8.row.col.f32.tf32.tf32.f32 "
        "{%0,%1,%2,%3}, {%4,%5,%6,%7}, {%8,%9}, {%0,%1,%2,%3};"
        : "+f"(d[0]), "+f"(d[1]), "+f"(d[2]), "+f"(d[3])
        : "r"(a[0]), "r"(a[1]), "r"(a[2]), "r"(a[3]), "r"(b[0]), "r"(b[1]));
}

// ---------------------------------------------------------------------------
// int32/int64 index detection.
// ---------------------------------------------------------------------------
__global__ void detect_k(const void* cp, const void* fci) {
    if (threadIdx.x != 0 || blockIdx.x != 0) return;
    const long long* p = (const long long*)cp;
    long long m = 0;
    for (int j = 1; j <= 8; ++j) {
        long long v = p[E_NUM / 2 - j];
        if (v < 0) v = (1LL << 40);
        if (v > m) m = v;
    }
    g_is32[0] = (m >= (long long)NALL) ? 1 : 0;
    const long long* q = (const long long*)fci;
    m = 0;
    for (int j = 1; j <= 8; ++j) {
        long long v = q[E_NUM / 2 - j];
        if (v < 0) v = (1LL << 40);
        if (v > m) m = v;
    }
    g_is32[1] = (m >= (long long)NALL) ? 1 : 0;
}

// ---------------------------------------------------------------------------
// convseg_k: fused index conversion + segment-boundary fill.
// ---------------------------------------------------------------------------
__device__ __forceinline__ int idx_at(const void* p, int is32, int e) {
    return is32 ? ((const int*)p)[e] : (int)((const long long*)p)[e];
}

__global__ void convseg_k(const void* cp, const void* fci) {
    int e = blockIdx.x * blockDim.x + threadIdx.x;
    if (e >= E_NUM) return;
    const int is0 = g_is32[0], is1 = g_is32[1];
    const int c = idx_at(cp, is0, e);
    g_cp[e] = c;
    g_fci[e] = idx_at(fci, is1, e);
    const int prev = (e == 0) ? -1 : idx_at(cp, is0, e - 1);
    for (int f = prev + 1; f <= c; ++f) g_segstart[f] = e;
    if (e == E_NUM - 1)
        for (int f = c + 1; f <= F_NUM; ++f) g_segstart[f] = E_NUM;
}

// ---------------------------------------------------------------------------
// wsplit_k: precompute tf32 hi/lo splits of W (256x64) once.
// ---------------------------------------------------------------------------
__global__ void wsplit_k(const float* __restrict__ w) {
    const int i = blockIdx.x * blockDim.x + threadIdx.x;
    if (i >= 2 * D_DIM * A_DIM) return;
    unsigned hi, lo;
    tf32_split(w[i], hi, lo);
    g_Whi[i] = hi;
    g_Wlo[i] = lo;
}

// ---------------------------------------------------------------------------
// pmma_k v2: P1/P2 via 3xTF32 tensor cores, A tile staged in smem,
// W splits precomputed. Block: 64 rows; 8 warps = 4 M-groups x 2 N-halves;
// warp tile 16M x 32N (4 n-tiles).
// ---------------------------------------------------------------------------
__global__ __launch_bounds__(256) void pmma_k(const float* __restrict__ feat,
                                              const float* __restrict__ hid) {
    const int tid = threadIdx.x;
    const int lane = tid & 31;
    const int wid = tid >> 5;

    const bool reg2 = (blockIdx.x >= PB1M);
    const int rbase = (reg2 ? (blockIdx.x - PB1M) : blockIdx.x) * PM_ROWS;
    const int limit = reg2 ? NALL : F_NUM;
    const int wbase = reg2 ? D_DIM : 0;
    float* const P = reg2 ? g_P2 : g_P1;

    __shared__ float sA[PM_ROWS * SA_STRIDE];

    // stage 64 rows x 128 cols, coalesced float4
    for (int i = tid; i < PM_ROWS * 32; i += 256) {
        const int r = i >> 5;
        const int c4 = i & 31;
        const int row = rbase + r;
        float4 v = make_float4(0.f, 0.f, 0.f, 0.f);
        if (row < limit) {
            const float* src;
            if (!reg2) src = feat + (size_t)row * D_DIM;
            else       src = (row < F_NUM) ? (feat + (size_t)row * D_DIM)
                                           : (hid + (size_t)(row - F_NUM) * D_DIM);
            v = ((const float4*)src)[c4];
        }
        *(float4*)&sA[r * SA_STRIDE + c4 * 4] = v;
    }
    __syncthreads();

    const int mloc = (wid & 3) * 16;       // local m offset
    const int nwp = (wid >> 2) * 32;       // n half
    const int gid = lane >> 2;             // 0..7
    const int tig = lane & 3;              // 0..3

    float acc[4][4];
#pragma unroll
    for (int t = 0; t < 4; ++t)
#pragma unroll
        for (int r = 0; r < 4; ++r) acc[t][r] = 0.f;

    for (int k = 0; k < D_DIM; k += 8) {
        // A fragments from smem (conflict-free via SA_STRIDE pad)
        unsigned ah[4], al[4];
        {
            const float a0 = sA[(mloc + gid)     * SA_STRIDE + k + tig];
            const float a1 = sA[(mloc + gid + 8) * SA_STRIDE + k + tig];
            const float a2 = sA[(mloc + gid)     * SA_STRIDE + k + tig + 4];
            const float a3 = sA[(mloc + gid + 8) * SA_STRIDE + k + tig + 4];
            tf32_split(a0, ah[0], al[0]);
            tf32_split(a1, ah[1], al[1]);
            tf32_split(a2, ah[2], al[2]);
            tf32_split(a3, ah[3], al[3]);
        }
        // B fragments: pre-split W from global (L1-resident)
        unsigned bh[4][2], bl[4][2];
#pragma unroll
        for (int t = 0; t < 4; ++t) {
            const int n = nwp + t * 8;
            const int i0 = (wbase + k + tig)     * A_DIM + n + gid;
            const int i1 = (wbase + k + 4 + tig) * A_DIM + n + gid;
            bh[t][0] = g_Whi[i0];
            bh[t][1] = g_Whi[i1];
            bl[t][0] = g_Wlo[i0];
            bl[t][1] = g_Wlo[i1];
        }
#pragma unroll
        for (int t = 0; t < 4; ++t) {
            mma_tf32(acc[t], ah, bh[t]);
            mma_tf32(acc[t], ah, bl[t]);
            mma_tf32(acc[t], al, bh[t]);
        }
    }

    // epilogue: float2 stores, rows guarded
    const int r0 = rbase + mloc + gid;
    const int r1 = r0 + 8;
#pragma unroll
    for (int t = 0; t < 4; ++t) {
        const int col = nwp + t * 8 + tig * 2;
        if (r0 < limit)
            *(float2*)(P + (size_t)r0 * A_DIM + col) = make_float2(acc[t][0], acc[t][1]);
        if (r1 < limit)
            *(float2*)(P + (size_t)r1 * A_DIM + col) = make_float2(acc[t][2], acc[t][3]);
    }
}

// ---------------------------------------------------------------------------
// sc_k: FUSED score + segment aggregation. One warp per feature segment.
// P1 row loaded once per segment; per edge: P2 row (coalesced), tanh-MLP
// score with full-warp butterfly reduce, then weighted emb accumulation.
// Deterministic: sequential edge order within each warp.
// ---------------------------------------------------------------------------
__device__ __forceinline__ const float4* emb_row(const float* feat, const float* hid, int fi) {
    return (const float4*)((fi < F_NUM) ? (feat + (size_t)fi * D_DIM)
                                        : (hid + (size_t)(fi - F_NUM) * D_DIM));
}

__global__ __launch_bounds__(256) void sc_k(const float* __restrict__ feat,
                                            const float* __restrict__ hid,
                                            const float* __restrict__ bias,
                                            const float* __restrict__ u,
                                            const float* __restrict__ corr) {
    const int lane = threadIdx.x & 31;
    const int f = blockIdx.x * 8 + (threadIdx.x >> 5);
    if (f >= F_NUM) return;

    const int lo = g_segstart[f];
    const int hiN = g_segstart[f + 1];

    const float b0 = bias[lane], b1 = bias[lane + 32];
    const float u0 = u[lane],    u1 = u[lane + 32];
    const float p1a = g_P1[(size_t)f * A_DIM + lane];
    const float p1b = g_P1[(size_t)f * A_DIM + lane + 32];

    float4 acc = make_float4(0.f, 0.f, 0.f, 0.f);
    float den = 0.f;

    for (int e = lo; e < hiN; ++e) {
        const int fi = g_fci[e];
        const float p2a = g_P2[(size_t)fi * A_DIM + lane];
        const float p2b = g_P2[(size_t)fi * A_DIM + lane + 32];
        float t = tanh_hw(p1a + p2a + b0) * u0 + tanh_hw(p1b + p2b + b1) * u1;
        t += __shfl_xor_sync(0xffffffffu, t, 1);
        t += __shfl_xor_sync(0xffffffffu, t, 2);
        t += __shfl_xor_sync(0xffffffffu, t, 4);
        t += __shfl_xor_sync(0xffffffffu, t, 8);
        t += __shfl_xor_sync(0xffffffffu, t, 16);
        const float s = __expf(t) * corr[e];
        const float4 v = emb_row(feat, hid, fi)[lane];
        acc.x += s * v.x; acc.y += s * v.y; acc.z += s * v.z; acc.w += s * v.w;
        den += s;
    }

    const float inv = (den != 0.f) ? (1.f / den) : 0.f;
    float4 o = make_float4(acc.x * inv, acc.y * inv, acc.z * inv, acc.w * inv);
    ((float4*)(g_context + (size_t)f * D_DIM))[lane] = o;
}

// ---------------------------------------------------------------------------
// g1 via tensor cores (EXACT R10/R11 version): 3xTF32 mma, partials + g2.
// ---------------------------------------------------------------------------
__global__ __launch_bounds__(256) void g1mma_k(const float* __restrict__ V) {
    const float* __restrict__ C = g_context;
    const int lane = threadIdx.x & 31;
    const int w = threadIdx.x >> 5;
    const int mg = w & 3;
    const int ng = w >> 2;
    const int mblk = blockIdx.x & 1;
    const int nblk = blockIdx.x >> 1;
    const int m_warp = mblk * 128 + mg * 32;
    const int n_warp = nblk * 64 + ng * 32;
    const int k0 = blockIdx.y * KCH;

    const int gid = lane >> 2;
    const int tig = lane & 3;

    float acc[2][4][4];
#pragma unroll
    for (int mt = 0; mt < 2; ++mt)
#pragma unroll
        for (int t = 0; t < 4; ++t)
#pragma unroll
            for (int r = 0; r < 4; ++r) acc[mt][t][r] = 0.f;

    for (int k = k0; k < k0 + KCH; k += 8) {
        unsigned ah[2][4], al[2][4];
#pragma unroll
        for (int mt = 0; mt < 2; ++mt) {
            const int m = m_warp + mt * 16;
            const float a0 = __ldg(V + (size_t)(m + gid)     * F_NUM + k + tig);
            const float a1 = __ldg(V + (size_t)(m + gid + 8) * F_NUM + k + tig);
            const float a2 = __ldg(V + (size_t)(m + gid)     * F_NUM + k + tig + 4);
            const float a3 = __ldg(V + (size_t)(m + gid + 8) * F_NUM + k + tig + 4);
            tf32_split(a0, ah[mt][0], al[mt][0]);
            tf32_split(a1, ah[mt][1], al[mt][1]);
            tf32_split(a2, ah[mt][2], al[mt][2]);
            tf32_split(a3, ah[mt][3], al[mt][3]);
        }
        unsigned bh[4][2], bl[4][2];
#pragma unroll
        for (int t = 0; t < 4; ++t) {
            const int n = n_warp + t * 8;
            const float b0 = C[(size_t)(k + tig)     * D_DIM + n + gid];
            const float b1 = C[(size_t)(k + 4 + tig) * D_DIM + n + gid];
            tf32_split(b0, bh[t][0], bl[t][0]);
            tf32_split(b1, bh[t][1], bl[t][1]);
        }
#pragma unroll
        for (int mt = 0; mt < 2; ++mt) {
#pragma unroll
            for (int t = 0; t < 4; ++t) {
                mma_tf32(acc[mt][t], ah[mt], bh[t]);
                mma_tf32(acc[mt][t], ah[mt], bl[t]);
                mma_tf32(acc[mt][t], al[mt], bh[t]);
            }
        }
    }

    float* part = g_partial + (size_t)blockIdx.y * (B_NUM * D_DIM);
#pragma unroll
    for (int mt = 0; mt < 2; ++mt) {
#pragma unroll
        for (int t = 0; t < 4; ++t) {
            const int row0 = m_warp + mt * 16 + gid;
            const int col  = n_warp + t * 8 + tig * 2;
            part[(size_t)row0 * D_DIM + col]           = acc[mt][t][0];
            part[(size_t)row0 * D_DIM + col + 1]       = acc[mt][t][1];
            part[(size_t)(row0 + 8) * D_DIM + col]     = acc[mt][t][2];
            part[(size_t)(row0 + 8) * D_DIM + col + 1] = acc[mt][t][3];
        }
    }
}

__global__ __launch_bounds__(256) void g2_k(float* __restrict__ out) {
    const int i = blockIdx.x * blockDim.x + threadIdx.x;
    if (i >= B_NUM * D_DIM) return;
    float s = 0.f;
#pragma unroll
    for (int j = 0; j < KSPLIT; ++j) s += g_partial[(size_t)j * (B_NUM * D_DIM) + i];
    out[i] = s;
}

// ---------------------------------------------------------------------------
extern "C" void kernel_launch(void* const* d_in, const int* in_sizes, int n_in,
                              void* d_out, int out_size) {
    const float* values = (const float*)d_in[0];
    const float* feat   = (const float*)d_in[1];
    const float* hid    = (const float*)d_in[2];
    const float* w      = (const float*)d_in[3];
    const float* bias   = (const float*)d_in[4];
    const float* u      = (const float*)d_in[5];
    const float* corr   = (const float*)d_in[6];
    const void*  cp     = d_in[7];
    const void*  fci    = d_in[8];
    float* out = (float*)d_out;

    detect_k<<<1, 32>>>(cp, fci);
    convseg_k<<<(E_NUM + 255) / 256, 256>>>(cp, fci);
    wsplit_k<<<(2 * D_DIM * A_DIM + 255) / 256, 256>>>(w);
    pmma_k<<<PB1M + PB2M, 256>>>(feat, hid);
    sc_k<<<F_NUM / 8, 256>>>(feat, hid, bias, u, corr);
    g1mma_k<<<dim3(4, KSPLIT), 256>>>(values);
    g2_k<<<(B_NUM * D_DIM + 255) / 256, 256>>>(out);
}

// round 13
// speedup vs baseline: 1.1960x; 1.1960x over previous
#include <cuda_runtime.h>

#define F_NUM 20000
#define H_NUM 40000
#define NALL  60000
#define E_NUM 640000
#define D_DIM 128
#define A_DIM 64
#define B_NUM 256
#define KSPLIT 50
#define KCH (F_NUM / KSPLIT)   // 400

// pmma tiling: 64 rows per block (A tile staged in smem), 8 warps:
// 4 M-groups (16 rows) x 2 N-halves (32 cols).
#define PM_ROWS 64
#define PB1M ((F_NUM + PM_ROWS - 1) / PM_ROWS)   // 313
#define PB2M ((NALL + PM_ROWS - 1) / PM_ROWS)    // 938
#define SA_STRIDE 132   // 128 + 4 pad -> conflict-free fragment LDS

// s_k layout: 8 warps/block, 4 edges/warp -> 32 edges per block.
#define S_EDGES_PER_BLOCK 32
#define S_GRID (E_NUM / S_EDGES_PER_BLOCK)   // 20000
static_assert(S_GRID * S_EDGES_PER_BLOCK == E_NUM, "s_k grid must cover all edges");
static_assert(KSPLIT * KCH == F_NUM, "split-K must tile F exactly");
static_assert(KCH % 8 == 0, "mma k-chunk must be a multiple of 8");

// Fragment-ordered W splits: [half][k8 (16)][n (64)][tig (4)][j (2)]
#define WF_ENTRIES (2 * 16 * 64 * 4 * 2)   // 16384

// ---- scratch (static device globals; no allocation) ----
__device__ float    g_P1[F_NUM * A_DIM];
__device__ float    g_P2[NALL * A_DIM];
__device__ float    g_scores[E_NUM];
__device__ float    g_context[F_NUM * D_DIM];
__device__ int      g_cp[E_NUM];
__device__ int      g_fci[E_NUM];
__device__ int      g_is32[2];
__device__ int      g_segstart[F_NUM + 1];
__device__ float    g_partial[KSPLIT * B_NUM * D_DIM];
__device__ unsigned g_Wfhi[WF_ENTRIES];
__device__ unsigned g_Wflo[WF_ENTRIES];

__device__ __forceinline__ float tanh_hw(float x) {
    float y;
    asm("tanh.approx.f32 %0, %1;" : "=f"(y) : "f"(x));
    return y;
}

// tf32 helpers for 3xTF32 GEMM
__device__ __forceinline__ unsigned tf32_of(float x) {
    unsigned r;
    asm("cvt.rna.tf32.f32 %0, %1;" : "=r"(r) : "f"(x));
    return r;
}
__device__ __forceinline__ void tf32_split(float x, unsigned& hi, unsigned& lo) {
    hi = tf32_of(x);
    lo = tf32_of(x - __uint_as_float(hi));
}
__device__ __forceinline__ void mma_tf32(float* d, const unsigned* a, const unsigned* b) {
    asm volatile(
        "mma.sync.aligned.m16n8k8.row.col.f32.tf32.tf32.f32 "
        "{%0,%1,%2,%3}, {%4,%5,%6,%7}, {%8,%9}, {%0,%1,%2,%3};"
        : "+f"(d[0]), "+f"(d[1]), "+f"(d[2]), "+f"(d[3])
        : "r"(a[0]), "r"(a[1]), "r"(a[2]), "r"(a[3]), "r"(b[0]), "r"(b[1]));
}

// ---------------------------------------------------------------------------
// int32/int64 index detection.
// ---------------------------------------------------------------------------
__global__ void detect_k(const void* cp, const void* fci) {
    if (threadIdx.x != 0 || blockIdx.x != 0) return;
    const long long* p = (const long long*)cp;
    long long m = 0;
    for (int j = 1; j <= 8; ++j) {
        long long v = p[E_NUM / 2 - j];
        if (v < 0) v = (1LL << 40);
        if (v > m) m = v;
    }
    g_is32[0] = (m >= (long long)NALL) ? 1 : 0;
    const long long* q = (const long long*)fci;
    m = 0;
    for (int j = 1; j <= 8; ++j) {
        long long v = q[E_NUM / 2 - j];
        if (v < 0) v = (1LL << 40);
        if (v > m) m = v;
    }
    g_is32[1] = (m >= (long long)NALL) ? 1 : 0;
}

// ---------------------------------------------------------------------------
// convseg_k: fused index conversion + segment-boundary fill.
// ---------------------------------------------------------------------------
__device__ __forceinline__ int idx_at(const void* p, int is32, int e) {
    return is32 ? ((const int*)p)[e] : (int)((const long long*)p)[e];
}

__global__ void convseg_k(const void* cp, const void* fci) {
    int e = blockIdx.x * blockDim.x + threadIdx.x;
    if (e >= E_NUM) return;
    const int is0 = g_is32[0], is1 = g_is32[1];
    const int c = idx_at(cp, is0, e);
    g_cp[e] = c;
    g_fci[e] = idx_at(fci, is1, e);
    const int prev = (e == 0) ? -1 : idx_at(cp, is0, e - 1);
    for (int f = prev + 1; f <= c; ++f) g_segstart[f] = e;
    if (e == E_NUM - 1)
        for (int f = c + 1; f <= F_NUM; ++f) g_segstart[f] = E_NUM;
}

// ---------------------------------------------------------------------------
// wsplit_k: fragment-ordered tf32 hi/lo splits of W.
// layout index = (((h*16 + k8)*64 + n)*4 + tig)*2 + j
// source      = w[(h*128 + k8*8 + tig + j*4)*A_DIM + n]
// A B-fragment load becomes one uint2 per (n-tile, hi/lo): lanes span 256
// contiguous bytes.
// ---------------------------------------------------------------------------
__global__ void wsplit_k(const float* __restrict__ w) {
    const int i = blockIdx.x * blockDim.x + threadIdx.x;
    if (i >= WF_ENTRIES) return;
    const int j   = i & 1;
    const int tig = (i >> 1) & 3;
    const int n   = (i >> 3) & 63;
    const int k8  = (i >> 9) & 15;
    const int h   = i >> 13;
    const float src = w[(size_t)(h * 128 + k8 * 8 + tig + j * 4) * A_DIM + n];
    unsigned hi, lo;
    tf32_split(src, hi, lo);
    g_Wfhi[i] = hi;
    g_Wflo[i] = lo;
}

// ---------------------------------------------------------------------------
// pmma_k v3: smem-staged A + fragment-ordered W (coalesced uint2 B loads).
// Block: 64 rows; 8 warps = 4 M-groups x 2 N-halves; warp tile 16M x 32N.
// ---------------------------------------------------------------------------
__global__ __launch_bounds__(256) void pmma_k(const float* __restrict__ feat,
                                              const float* __restrict__ hid) {
    const int tid = threadIdx.x;
    const int lane = tid & 31;
    const int wid = tid >> 5;

    const bool reg2 = (blockIdx.x >= PB1M);
    const int rbase = (reg2 ? (blockIdx.x - PB1M) : blockIdx.x) * PM_ROWS;
    const int limit = reg2 ? NALL : F_NUM;
    const int hsel = reg2 ? 1 : 0;
    float* const P = reg2 ? g_P2 : g_P1;

    __shared__ float sA[PM_ROWS * SA_STRIDE];

    // stage 64 rows x 128 cols, coalesced float4
    for (int i = tid; i < PM_ROWS * 32; i += 256) {
        const int r = i >> 5;
        const int c4 = i & 31;
        const int row = rbase + r;
        float4 v = make_float4(0.f, 0.f, 0.f, 0.f);
        if (row < limit) {
            const float* src;
            if (!reg2) src = feat + (size_t)row * D_DIM;
            else       src = (row < F_NUM) ? (feat + (size_t)row * D_DIM)
                                           : (hid + (size_t)(row - F_NUM) * D_DIM);
            v = ((const float4*)src)[c4];
        }
        *(float4*)&sA[r * SA_STRIDE + c4 * 4] = v;
    }
    __syncthreads();

    const int mloc = (wid & 3) * 16;       // local m offset
    const int nwp = (wid >> 2) * 32;       // n half
    const int gid = lane >> 2;             // 0..7
    const int tig = lane & 3;              // 0..3

    float acc[4][4];
#pragma unroll
    for (int t = 0; t < 4; ++t)
#pragma unroll
        for (int r = 0; r < 4; ++r) acc[t][r] = 0.f;

    for (int k8 = 0; k8 < 16; ++k8) {
        const int k = k8 * 8;
        // A fragments from smem (conflict-free via SA_STRIDE pad)
        unsigned ah[4], al[4];
        {
            const float a0 = sA[(mloc + gid)     * SA_STRIDE + k + tig];
            const float a1 = sA[(mloc + gid + 8) * SA_STRIDE + k + tig];
            const float a2 = sA[(mloc + gid)     * SA_STRIDE + k + tig + 4];
            const float a3 = sA[(mloc + gid + 8) * SA_STRIDE + k + tig + 4];
            tf32_split(a0, ah[0], al[0]);
            tf32_split(a1, ah[1], al[1]);
            tf32_split(a2, ah[2], al[2]);
            tf32_split(a3, ah[3], al[3]);
        }
        // B fragments: fragment-ordered pre-split W, one uint2 per (tile, hi/lo)
        unsigned bh[4][2], bl[4][2];
#pragma unroll
        for (int t = 0; t < 4; ++t) {
            const int n = nwp + t * 8 + gid;
            const int base = (((hsel * 16 + k8) * 64 + n) * 4 + tig) * 2;
            const uint2 vh = *(const uint2*)&g_Wfhi[base];
            const uint2 vl = *(const uint2*)&g_Wflo[base];
            bh[t][0] = vh.x; bh[t][1] = vh.y;
            bl[t][0] = vl.x; bl[t][1] = vl.y;
        }
#pragma unroll
        for (int t = 0; t < 4; ++t) {
            mma_tf32(acc[t], ah, bh[t]);
            mma_tf32(acc[t], ah, bl[t]);
            mma_tf32(acc[t], al, bh[t]);
        }
    }

    // epilogue: float2 stores, rows guarded
    const int r0 = rbase + mloc + gid;
    const int r1 = r0 + 8;
#pragma unroll
    for (int t = 0; t < 4; ++t) {
        const int col = nwp + t * 8 + tig * 2;
        if (r0 < limit)
            *(float2*)(P + (size_t)r0 * A_DIM + col) = make_float2(acc[t][0], acc[t][1]);
        if (r1 < limit)
            *(float2*)(P + (size_t)r1 * A_DIM + col) = make_float2(acc[t][2], acc[t][3]);
    }
}

// ---------------------------------------------------------------------------
// S kernel: 8-lane cooperative per edge (EXACT R8 version, measured 35.6us).
// ---------------------------------------------------------------------------
__global__ __launch_bounds__(256) void s_k(const float* __restrict__ bias,
                                           const float* __restrict__ u,
                                           const float* __restrict__ corr) {
    const int tid = threadIdx.x;
    const int lane = tid & 31;
    const int grp = lane >> 3;
    const int l = lane & 7;
    const int warp = (blockIdx.x * 256 + tid) >> 5;
    const int e = warp * 4 + grp;

    const float4 b0 = ((const float4*)bias)[l];
    const float4 b1 = ((const float4*)bias)[l + 8];
    const float4 u0 = ((const float4*)u)[l];
    const float4 u1 = ((const float4*)u)[l + 8];

    const int c = g_cp[e];
    const int fi = g_fci[e];
    const float4* p1 = (const float4*)(g_P1 + (size_t)c * A_DIM);
    const float4* p2 = (const float4*)(g_P2 + (size_t)fi * A_DIM);
    const float4 x0 = p1[l], x1 = p1[l + 8];
    const float4 y0 = p2[l], y1 = p2[l + 8];

    float t = tanh_hw(x0.x + y0.x + b0.x) * u0.x
            + tanh_hw(x0.y + y0.y + b0.y) * u0.y
            + tanh_hw(x0.z + y0.z + b0.z) * u0.z
            + tanh_hw(x0.w + y0.w + b0.w) * u0.w
            + tanh_hw(x1.x + y1.x + b1.x) * u1.x
            + tanh_hw(x1.y + y1.y + b1.y) * u1.y
            + tanh_hw(x1.z + y1.z + b1.z) * u1.z
            + tanh_hw(x1.w + y1.w + b1.w) * u1.w;

    t += __shfl_xor_sync(0xffffffffu, t, 1);
    t += __shfl_xor_sync(0xffffffffu, t, 2);
    t += __shfl_xor_sync(0xffffffffu, t, 4);
    if (l == 0) g_scores[e] = __expf(t) * corr[e];
}

// ---------------------------------------------------------------------------
// C kernel: warp per feature segment (EXACT R8 version).
// ---------------------------------------------------------------------------
__device__ __forceinline__ const float4* emb_row(const float* feat, const float* hid, int fi) {
    return (const float4*)((fi < F_NUM) ? (feat + (size_t)fi * D_DIM)
                                        : (hid + (size_t)(fi - F_NUM) * D_DIM));
}

__global__ __launch_bounds__(256) void c_k(const float* __restrict__ feat,
                                           const float* __restrict__ hid) {
    const int lane = threadIdx.x & 31;
    const int f = blockIdx.x * 8 + (threadIdx.x >> 5);
    if (f >= F_NUM) return;

    const int lo = g_segstart[f];
    const int hiN = g_segstart[f + 1];

    float4 acc = make_float4(0.f, 0.f, 0.f, 0.f);
    float den = 0.f;
    int e = lo;
    for (; e + 4 <= hiN; e += 4) {
        const float s0 = g_scores[e + 0];
        const float s1 = g_scores[e + 1];
        const float s2 = g_scores[e + 2];
        const float s3 = g_scores[e + 3];
        const float4 v0 = emb_row(feat, hid, g_fci[e + 0])[lane];
        const float4 v1 = emb_row(feat, hid, g_fci[e + 1])[lane];
        const float4 v2 = emb_row(feat, hid, g_fci[e + 2])[lane];
        const float4 v3 = emb_row(feat, hid, g_fci[e + 3])[lane];
        acc.x += s0 * v0.x + s1 * v1.x + s2 * v2.x + s3 * v3.x;
        acc.y += s0 * v0.y + s1 * v1.y + s2 * v2.y + s3 * v3.y;
        acc.z += s0 * v0.z + s1 * v1.z + s2 * v2.z + s3 * v3.z;
        acc.w += s0 * v0.w + s1 * v1.w + s2 * v2.w + s3 * v3.w;
        den += (s0 + s1) + (s2 + s3);
    }
    for (; e < hiN; ++e) {
        const float s = g_scores[e];
        const float4 v = emb_row(feat, hid, g_fci[e])[lane];
        acc.x += s * v.x; acc.y += s * v.y; acc.z += s * v.z; acc.w += s * v.w;
        den += s;
    }
    const float inv = (den != 0.f) ? (1.f / den) : 0.f;
    float4 o = make_float4(acc.x * inv, acc.y * inv, acc.z * inv, acc.w * inv);
    ((float4*)(g_context + (size_t)f * D_DIM))[lane] = o;
}

// ---------------------------------------------------------------------------
// g1 via tensor cores (EXACT R10/R11 version): 3xTF32 mma, partials + g2.
// ---------------------------------------------------------------------------
__global__ __launch_bounds__(256) void g1mma_k(const float* __restrict__ V) {
    const float* __restrict__ C = g_context;
    const int lane = threadIdx.x & 31;
    const int w = threadIdx.x >> 5;
    const int mg = w & 3;
    const int ng = w >> 2;
    const int mblk = blockIdx.x & 1;
    const int nblk = blockIdx.x >> 1;
    const int m_warp = mblk * 128 + mg * 32;
    const int n_warp = nblk * 64 + ng * 32;
    const int k0 = blockIdx.y * KCH;

    const int gid = lane >> 2;
    const int tig = lane & 3;

    float acc[2][4][4];
#pragma unroll
    for (int mt = 0; mt < 2; ++mt)
#pragma unroll
        for (int t = 0; t < 4; ++t)
#pragma unroll
            for (int r = 0; r < 4; ++r) acc[mt][t][r] = 0.f;

    for (int k = k0; k < k0 + KCH; k += 8) {
        unsigned ah[2][4], al[2][4];
#pragma unroll
        for (int mt = 0; mt < 2; ++mt) {
            const int m = m_warp + mt * 16;
            const float a0 = __ldg(V + (size_t)(m + gid)     * F_NUM + k + tig);
            const float a1 = __ldg(V + (size_t)(m + gid + 8) * F_NUM + k + tig);
            const float a2 = __ldg(V + (size_t)(m + gid)     * F_NUM + k + tig + 4);
            const float a3 = __ldg(V + (size_t)(m + gid + 8) * F_NUM + k + tig + 4);
            tf32_split(a0, ah[mt][0], al[mt][0]);
            tf32_split(a1, ah[mt][1], al[mt][1]);
            tf32_split(a2, ah[mt][2], al[mt][2]);
            tf32_split(a3, ah[mt][3], al[mt][3]);
        }
        unsigned bh[4][2], bl[4][2];
#pragma unroll
        for (int t = 0; t < 4; ++t) {
            const int n = n_warp + t * 8;
            const float b0 = C[(size_t)(k + tig)     * D_DIM + n + gid];
            const float b1 = C[(size_t)(k + 4 + tig) * D_DIM + n + gid];
            tf32_split(b0, bh[t][0], bl[t][0]);
            tf32_split(b1, bh[t][1], bl[t][1]);
        }
#pragma unroll
        for (int mt = 0; mt < 2; ++mt) {
#pragma unroll
            for (int t = 0; t < 4; ++t) {
                mma_tf32(acc[mt][t], ah[mt], bh[t]);
                mma_tf32(acc[mt][t], ah[mt], bl[t]);
                mma_tf32(acc[mt][t], al[mt], bh[t]);
            }
        }
    }

    float* part = g_partial + (size_t)blockIdx.y * (B_NUM * D_DIM);
#pragma unroll
    for (int mt = 0; mt < 2; ++mt) {
#pragma unroll
        for (int t = 0; t < 4; ++t) {
            const int row0 = m_warp + mt * 16 + gid;
            const int col  = n_warp + t * 8 + tig * 2;
            part[(size_t)row0 * D_DIM + col]           = acc[mt][t][0];
            part[(size_t)row0 * D_DIM + col + 1]       = acc[mt][t][1];
            part[(size_t)(row0 + 8) * D_DIM + col]     = acc[mt][t][2];
            part[(size_t)(row0 + 8) * D_DIM + col + 1] = acc[mt][t][3];
        }
    }
}

__global__ __launch_bounds__(256) void g2_k(float* __restrict__ out) {
    const int i = blockIdx.x * blockDim.x + threadIdx.x;
    if (i >= B_NUM * D_DIM) return;
    float s = 0.f;
#pragma unroll
    for (int j = 0; j < KSPLIT; ++j) s += g_partial[(size_t)j * (B_NUM * D_DIM) + i];
    out[i] = s;
}

// ---------------------------------------------------------------------------
extern "C" void kernel_launch(void* const* d_in, const int* in_sizes, int n_in,
                              void* d_out, int out_size) {
    const float* values = (const float*)d_in[0];
    const float* feat   = (const float*)d_in[1];
    const float* hid    = (const float*)d_in[2];
    const float* w      = (const float*)d_in[3];
    const float* bias   = (const float*)d_in[4];
    const float* u      = (const float*)d_in[5];
    const float* corr   = (const float*)d_in[6];
    const void*  cp     = d_in[7];
    const void*  fci    = d_in[8];
    float* out = (float*)d_out;

    detect_k<<<1, 32>>>(cp, fci);
    convseg_k<<<(E_NUM + 255) / 256, 256>>>(cp, fci);
    wsplit_k<<<(WF_ENTRIES + 255) / 256, 256>>>(w);
    pmma_k<<<PB1M + PB2M, 256>>>(feat, hid);
    s_k<<<S_GRID, 256>>>(bias, u, corr);
    c_k<<<F_NUM / 8, 256>>>(feat, hid);
    g1mma_k<<<dim3(4, KSPLIT), 256>>>(values);
    g2_k<<<(B_NUM * D_DIM + 255) / 256, 256>>>(out);
}

// round 14
// speedup vs baseline: 1.2220x; 1.0217x over previous
#include <cuda_runtime.h>

#define F_NUM 20000
#define H_NUM 40000
#define NALL  60000
#define E_NUM 640000
#define D_DIM 128
#define A_DIM 64
#define B_NUM 256
#define KSPLIT 50
#define KCH (F_NUM / KSPLIT)   // 400

// pmma tiling: 64 rows per block, 4 warps = 2 M-groups (32 rows) x 2 N-halves.
#define PM_ROWS 64
#define PB1M ((F_NUM + PM_ROWS - 1) / PM_ROWS)   // 313
#define PB2M ((NALL + PM_ROWS - 1) / PM_ROWS)    // 938
#define SA_STRIDE 132   // 128 + 4 pad -> conflict-free fragment LDS

// s_k layout: 8 warps/block, 4 edges/warp -> 32 edges per block.
#define S_EDGES_PER_BLOCK 32
#define S_GRID (E_NUM / S_EDGES_PER_BLOCK)   // 20000
static_assert(S_GRID * S_EDGES_PER_BLOCK == E_NUM, "s_k grid must cover all edges");
static_assert(KSPLIT * KCH == F_NUM, "split-K must tile F exactly");
static_assert(KCH % 8 == 0, "mma k-chunk must be a multiple of 8");

// Fragment-ordered W splits: [half][k8 (16)][n (64)][tig (4)][j (2)]
#define WF_ENTRIES (2 * 16 * 64 * 4 * 2)   // 16384

// ---- scratch (static device globals; no allocation) ----
__device__ float    g_P1[F_NUM * A_DIM];
__device__ float    g_P2[NALL * A_DIM];
__device__ float    g_scores[E_NUM];
__device__ float    g_context[F_NUM * D_DIM];
__device__ int      g_cp[E_NUM];
__device__ int      g_fci[E_NUM];
__device__ int      g_segstart[F_NUM + 1];
__device__ float    g_partial[KSPLIT * B_NUM * D_DIM];
__device__ unsigned g_Wfhi[WF_ENTRIES];
__device__ unsigned g_Wflo[WF_ENTRIES];

__device__ __forceinline__ float tanh_hw(float x) {
    float y;
    asm("tanh.approx.f32 %0, %1;" : "=f"(y) : "f"(x));
    return y;
}

// tf32 helpers for 3xTF32 GEMM
__device__ __forceinline__ unsigned tf32_of(float x) {
    unsigned r;
    asm("cvt.rna.tf32.f32 %0, %1;" : "=r"(r) : "f"(x));
    return r;
}
__device__ __forceinline__ void tf32_split(float x, unsigned& hi, unsigned& lo) {
    hi = tf32_of(x);
    lo = tf32_of(x - __uint_as_float(hi));
}
__device__ __forceinline__ void mma_tf32(float* d, const unsigned* a, const unsigned* b) {
    asm volatile(
        "mma.sync.aligned.m16n8k8.row.col.f32.tf32.tf32.f32 "
        "{%0,%1,%2,%3}, {%4,%5,%6,%7}, {%8,%9}, {%0,%1,%2,%3};"
        : "+f"(d[0]), "+f"(d[1]), "+f"(d[2]), "+f"(d[3])
        : "r"(a[0]), "r"(a[1]), "r"(a[2]), "r"(a[3]), "r"(b[0]), "r"(b[1]));
}

// ---------------------------------------------------------------------------
// int32/int64 detection as a device helper: probe tail as int64; int32 data
// yields high-word >= NALL. Loads are L1/L2-cached across blocks.
// ---------------------------------------------------------------------------
__device__ __forceinline__ int detect32(const void* p) {
    const long long* q = (const long long*)p;
    long long m = 0;
#pragma unroll
    for (int j = 1; j <= 8; ++j) {
        long long v = q[E_NUM / 2 - j];
        if (v < 0) v = (1LL << 40);
        if (v > m) m = v;
    }
    return (m >= (long long)NALL) ? 1 : 0;
}

// ---------------------------------------------------------------------------
// convseg_k: fused dtype detect + index conversion + segment-boundary fill.
// segstart[f] = first e with cp[e] >= f (cp sorted).
// ---------------------------------------------------------------------------
__device__ __forceinline__ int idx_at(const void* p, int is32, int e) {
    return is32 ? ((const int*)p)[e] : (int)((const long long*)p)[e];
}

__global__ void convseg_k(const void* cp, const void* fci) {
    __shared__ int sis[2];
    if (threadIdx.x == 0) {
        sis[0] = detect32(cp);
        sis[1] = detect32(fci);
    }
    __syncthreads();
    const int is0 = sis[0], is1 = sis[1];

    int e = blockIdx.x * blockDim.x + threadIdx.x;
    if (e >= E_NUM) return;
    const int c = idx_at(cp, is0, e);
    g_cp[e] = c;
    g_fci[e] = idx_at(fci, is1, e);
    const int prev = (e == 0) ? -1 : idx_at(cp, is0, e - 1);
    for (int f = prev + 1; f <= c; ++f) g_segstart[f] = e;
    if (e == E_NUM - 1)
        for (int f = c + 1; f <= F_NUM; ++f) g_segstart[f] = E_NUM;
}

// ---------------------------------------------------------------------------
// wsplit_k: fragment-ordered tf32 hi/lo splits of W.
// layout index = (((h*16 + k8)*64 + n)*4 + tig)*2 + j
// source      = w[(h*128 + k8*8 + tig + j*4)*A_DIM + n]
// ---------------------------------------------------------------------------
__global__ void wsplit_k(const float* __restrict__ w) {
    const int i = blockIdx.x * blockDim.x + threadIdx.x;
    if (i >= WF_ENTRIES) return;
    const int j   = i & 1;
    const int tig = (i >> 1) & 3;
    const int n   = (i >> 3) & 63;
    const int k8  = (i >> 9) & 15;
    const int h   = i >> 13;
    const float src = w[(size_t)(h * 128 + k8 * 8 + tig + j * 4) * A_DIM + n];
    unsigned hi, lo;
    tf32_split(src, hi, lo);
    g_Wfhi[i] = hi;
    g_Wflo[i] = lo;
}

// ---------------------------------------------------------------------------
// pmma_k v4: smem-staged A + fragment-ordered W, 32Mx32N warp tiles.
// Block: 128 threads, 4 warps = 2 M-groups x 2 N-halves; each warp does
// 2 m-tiles x 4 n-tiles (acc 32 regs). B loads amortized over 2x MMAs.
// ---------------------------------------------------------------------------
__global__ __launch_bounds__(128) void pmma_k(const float* __restrict__ feat,
                                              const float* __restrict__ hid) {
    const int tid = threadIdx.x;
    const int lane = tid & 31;
    const int wid = tid >> 5;

    const bool reg2 = (blockIdx.x >= PB1M);
    const int rbase = (reg2 ? (blockIdx.x - PB1M) : blockIdx.x) * PM_ROWS;
    const int limit = reg2 ? NALL : F_NUM;
    const int hsel = reg2 ? 1 : 0;
    float* const P = reg2 ? g_P2 : g_P1;

    __shared__ float sA[PM_ROWS * SA_STRIDE];

    // stage 64 rows x 128 cols, coalesced float4 (16 iters per thread)
    for (int i = tid; i < PM_ROWS * 32; i += 128) {
        const int r = i >> 5;
        const int c4 = i & 31;
        const int row = rbase + r;
        float4 v = make_float4(0.f, 0.f, 0.f, 0.f);
        if (row < limit) {
            const float* src;
            if (!reg2) src = feat + (size_t)row * D_DIM;
            else       src = (row < F_NUM) ? (feat + (size_t)row * D_DIM)
                                           : (hid + (size_t)(row - F_NUM) * D_DIM);
            v = ((const float4*)src)[c4];
        }
        *(float4*)&sA[r * SA_STRIDE + c4 * 4] = v;
    }
    __syncthreads();

    const int mloc = (wid & 1) * 32;       // M group: rows [mloc, mloc+32)
    const int nwp = (wid >> 1) * 32;       // N half
    const int gid = lane >> 2;             // 0..7
    const int tig = lane & 3;              // 0..3

    float acc[2][4][4];
#pragma unroll
    for (int mt = 0; mt < 2; ++mt)
#pragma unroll
        for (int t = 0; t < 4; ++t)
#pragma unroll
            for (int r = 0; r < 4; ++r) acc[mt][t][r] = 0.f;

    for (int k8 = 0; k8 < 16; ++k8) {
        const int k = k8 * 8;
        // A fragments for 2 m-tiles from smem (pad -> conflict-free)
        unsigned ah[2][4], al[2][4];
#pragma unroll
        for (int mt = 0; mt < 2; ++mt) {
            const int m = mloc + mt * 16;
            const float a0 = sA[(m + gid)     * SA_STRIDE + k + tig];
            const float a1 = sA[(m + gid + 8) * SA_STRIDE + k + tig];
            const float a2 = sA[(m + gid)     * SA_STRIDE + k + tig + 4];
            const float a3 = sA[(m + gid + 8) * SA_STRIDE + k + tig + 4];
            tf32_split(a0, ah[mt][0], al[mt][0]);
            tf32_split(a1, ah[mt][1], al[mt][1]);
            tf32_split(a2, ah[mt][2], al[mt][2]);
            tf32_split(a3, ah[mt][3], al[mt][3]);
        }
        // B fragments: fragment-ordered pre-split W, one uint2 per (tile, hi/lo)
        unsigned bh[4][2], bl[4][2];
#pragma unroll
        for (int t = 0; t < 4; ++t) {
            const int n = nwp + t * 8 + gid;
            const int base = (((hsel * 16 + k8) * 64 + n) * 4 + tig) * 2;
            const uint2 vh = *(const uint2*)&g_Wfhi[base];
            const uint2 vl = *(const uint2*)&g_Wflo[base];
            bh[t][0] = vh.x; bh[t][1] = vh.y;
            bl[t][0] = vl.x; bl[t][1] = vl.y;
        }
#pragma unroll
        for (int mt = 0; mt < 2; ++mt) {
#pragma unroll
            for (int t = 0; t < 4; ++t) {
                mma_tf32(acc[mt][t], ah[mt], bh[t]);
                mma_tf32(acc[mt][t], ah[mt], bl[t]);
                mma_tf32(acc[mt][t], al[mt], bh[t]);
            }
        }
    }

    // epilogue: float2 stores, rows guarded
#pragma unroll
    for (int mt = 0; mt < 2; ++mt) {
        const int r0 = rbase + mloc + mt * 16 + gid;
        const int r1 = r0 + 8;
#pragma unroll
        for (int t = 0; t < 4; ++t) {
            const int col = nwp + t * 8 + tig * 2;
            if (r0 < limit)
                *(float2*)(P + (size_t)r0 * A_DIM + col) = make_float2(acc[mt][t][0], acc[mt][t][1]);
            if (r1 < limit)
                *(float2*)(P + (size_t)r1 * A_DIM + col) = make_float2(acc[mt][t][2], acc[mt][t][3]);
        }
    }
}

// ---------------------------------------------------------------------------
// S kernel: 8-lane cooperative per edge (EXACT R8 version, measured 35.6us).
// ---------------------------------------------------------------------------
__global__ __launch_bounds__(256) void s_k(const float* __restrict__ bias,
                                           const float* __restrict__ u,
                                           const float* __restrict__ corr) {
    const int tid = threadIdx.x;
    const int lane = tid & 31;
    const int grp = lane >> 3;
    const int l = lane & 7;
    const int warp = (blockIdx.x * 256 + tid) >> 5;
    const int e = warp * 4 + grp;

    const float4 b0 = ((const float4*)bias)[l];
    const float4 b1 = ((const float4*)bias)[l + 8];
    const float4 u0 = ((const float4*)u)[l];
    const float4 u1 = ((const float4*)u)[l + 8];

    const int c = g_cp[e];
    const int fi = g_fci[e];
    const float4* p1 = (const float4*)(g_P1 + (size_t)c * A_DIM);
    const float4* p2 = (const float4*)(g_P2 + (size_t)fi * A_DIM);
    const float4 x0 = p1[l], x1 = p1[l + 8];
    const float4 y0 = p2[l], y1 = p2[l + 8];

    float t = tanh_hw(x0.x + y0.x + b0.x) * u0.x
            + tanh_hw(x0.y + y0.y + b0.y) * u0.y
            + tanh_hw(x0.z + y0.z + b0.z) * u0.z
            + tanh_hw(x0.w + y0.w + b0.w) * u0.w
            + tanh_hw(x1.x + y1.x + b1.x) * u1.x
            + tanh_hw(x1.y + y1.y + b1.y) * u1.y
            + tanh_hw(x1.z + y1.z + b1.z) * u1.z
            + tanh_hw(x1.w + y1.w + b1.w) * u1.w;

    t += __shfl_xor_sync(0xffffffffu, t, 1);
    t += __shfl_xor_sync(0xffffffffu, t, 2);
    t += __shfl_xor_sync(0xffffffffu, t, 4);
    if (l == 0) g_scores[e] = __expf(t) * corr[e];
}

// ---------------------------------------------------------------------------
// C kernel: warp per feature segment (EXACT R8 version).
// ---------------------------------------------------------------------------
__device__ __forceinline__ const float4* emb_row(const float* feat, const float* hid, int fi) {
    return (const float4*)((fi < F_NUM) ? (feat + (size_t)fi * D_DIM)
                                        : (hid + (size_t)(fi - F_NUM) * D_DIM));
}

__global__ __launch_bounds__(256) void c_k(const float* __restrict__ feat,
                                           const float* __restrict__ hid) {
    const int lane = threadIdx.x & 31;
    const int f = blockIdx.x * 8 + (threadIdx.x >> 5);
    if (f >= F_NUM) return;

    const int lo = g_segstart[f];
    const int hiN = g_segstart[f + 1];

    float4 acc = make_float4(0.f, 0.f, 0.f, 0.f);
    float den = 0.f;
    int e = lo;
    for (; e + 4 <= hiN; e += 4) {
        const float s0 = g_scores[e + 0];
        const float s1 = g_scores[e + 1];
        const float s2 = g_scores[e + 2];
        const float s3 = g_scores[e + 3];
        const float4 v0 = emb_row(feat, hid, g_fci[e + 0])[lane];
        const float4 v1 = emb_row(feat, hid, g_fci[e + 1])[lane];
        const float4 v2 = emb_row(feat, hid, g_fci[e + 2])[lane];
        const float4 v3 = emb_row(feat, hid, g_fci[e + 3])[lane];
        acc.x += s0 * v0.x + s1 * v1.x + s2 * v2.x + s3 * v3.x;
        acc.y += s0 * v0.y + s1 * v1.y + s2 * v2.y + s3 * v3.y;
        acc.z += s0 * v0.z + s1 * v1.z + s2 * v2.z + s3 * v3.z;
        acc.w += s0 * v0.w + s1 * v1.w + s2 * v2.w + s3 * v3.w;
        den += (s0 + s1) + (s2 + s3);
    }
    for (; e < hiN; ++e) {
        const float s = g_scores[e];
        const float4 v = emb_row(feat, hid, g_fci[e])[lane];
        acc.x += s * v.x; acc.y += s * v.y; acc.z += s * v.z; acc.w += s * v.w;
        den += s;
    }
    const float inv = (den != 0.f) ? (1.f / den) : 0.f;
    float4 o = make_float4(acc.x * inv, acc.y * inv, acc.z * inv, acc.w * inv);
    ((float4*)(g_context + (size_t)f * D_DIM))[lane] = o;
}

// ---------------------------------------------------------------------------
// g1 via tensor cores (EXACT R10-R13 version): 3xTF32 mma, partials + g2.
// ---------------------------------------------------------------------------
__global__ __launch_bounds__(256) void g1mma_k(const float* __restrict__ V) {
    const float* __restrict__ C = g_context;
    const int lane = threadIdx.x & 31;
    const int w = threadIdx.x >> 5;
    const int mg = w & 3;
    const int ng = w >> 2;
    const int mblk = blockIdx.x & 1;
    const int nblk = blockIdx.x >> 1;
    const int m_warp = mblk * 128 + mg * 32;
    const int n_warp = nblk * 64 + ng * 32;
    const int k0 = blockIdx.y * KCH;

    const int gid = lane >> 2;
    const int tig = lane & 3;

    float acc[2][4][4];
#pragma unroll
    for (int mt = 0; mt < 2; ++mt)
#pragma unroll
        for (int t = 0; t < 4; ++t)
#pragma unroll
            for (int r = 0; r < 4; ++r) acc[mt][t][r] = 0.f;

    for (int k = k0; k < k0 + KCH; k += 8) {
        unsigned ah[2][4], al[2][4];
#pragma unroll
        for (int mt = 0; mt < 2; ++mt) {
            const int m = m_warp + mt * 16;
            const float a0 = __ldg(V + (size_t)(m + gid)     * F_NUM + k + tig);
            const float a1 = __ldg(V + (size_t)(m + gid + 8) * F_NUM + k + tig);
            const float a2 = __ldg(V + (size_t)(m + gid)     * F_NUM + k + tig + 4);
            const float a3 = __ldg(V + (size_t)(m + gid + 8) * F_NUM + k + tig + 4);
            tf32_split(a0, ah[mt][0], al[mt][0]);
            tf32_split(a1, ah[mt][1], al[mt][1]);
            tf32_split(a2, ah[mt][2], al[mt][2]);
            tf32_split(a3, ah[mt][3], al[mt][3]);
        }
        unsigned bh[4][2], bl[4][2];
#pragma unroll
        for (int t = 0; t < 4; ++t) {
            const int n = n_warp + t * 8;
            const float b0 = C[(size_t)(k + tig)     * D_DIM + n + gid];
            const float b1 = C[(size_t)(k + 4 + tig) * D_DIM + n + gid];
            tf32_split(b0, bh[t][0], bl[t][0]);
            tf32_split(b1, bh[t][1], bl[t][1]);
        }
#pragma unroll
        for (int mt = 0; mt < 2; ++mt) {
#pragma unroll
            for (int t = 0; t < 4; ++t) {
                mma_tf32(acc[mt][t], ah[mt], bh[t]);
                mma_tf32(acc[mt][t], ah[mt], bl[t]);
                mma_tf32(acc[mt][t], al[mt], bh[t]);
            }
        }
    }

    float* part = g_partial + (size_t)blockIdx.y * (B_NUM * D_DIM);
#pragma unroll
    for (int mt = 0; mt < 2; ++mt) {
#pragma unroll
        for (int t = 0; t < 4; ++t) {
            const int row0 = m_warp + mt * 16 + gid;
            const int col  = n_warp + t * 8 + tig * 2;
            part[(size_t)row0 * D_DIM + col]           = acc[mt][t][0];
            part[(size_t)row0 * D_DIM + col + 1]       = acc[mt][t][1];
            part[(size_t)(row0 + 8) * D_DIM + col]     = acc[mt][t][2];
            part[(size_t)(row0 + 8) * D_DIM + col + 1] = acc[mt][t][3];
        }
    }
}

__global__ __launch_bounds__(256) void g2_k(float* __restrict__ out) {
    const int i = blockIdx.x * blockDim.x + threadIdx.x;
    if (i >= B_NUM * D_DIM) return;
    float s = 0.f;
#pragma unroll
    for (int j = 0; j < KSPLIT; ++j) s += g_partial[(size_t)j * (B_NUM * D_DIM) + i];
    out[i] = s;
}

// ---------------------------------------------------------------------------
extern "C" void kernel_launch(void* const* d_in, const int* in_sizes, int n_in,
                              void* d_out, int out_size) {
    const float* values = (const float*)d_in[0];
    const float* feat   = (const float*)d_in[1];
    const float* hid    = (const float*)d_in[2];
    const float* w      = (const float*)d_in[3];
    const float* bias   = (const float*)d_in[4];
    const float* u      = (const float*)d_in[5];
    const float* corr   = (const float*)d_in[6];
    const void*  cp     = d_in[7];
    const void*  fci    = d_in[8];
    float* out = (float*)d_out;

    wsplit_k<<<(WF_ENTRIES + 255) / 256, 256>>>(w);
    pmma_k<<<PB1M + PB2M, 128>>>(feat, hid);
    convseg_k<<<(E_NUM + 255) / 256, 256>>>(cp, fci);
    s_k<<<S_GRID, 256>>>(bias, u, corr);
    c_k<<<F_NUM / 8, 256>>>(feat, hid);
    g1mma_k<<<dim3(4, KSPLIT), 256>>>(values);
    g2_k<<<(B_NUM * D_DIM + 255) / 256, 256>>>(out);
}